// round 4
// baseline (speedup 1.0000x reference)
#include <cuda_runtime.h>
#include <math.h>

#define NN 8192

// Warp-per-row, g staged in shared memory.
// CTA = 256 threads = 8 warps = 8 rows; grid = 1024 (single wave at occ 7).
// g (32 KB) is loaded to smem once per CTA; the mainloop reads g via the
// shared pipe (LDS) instead of L1tex, halving L1tex wavefront pressure.
// w streamed evict-first (__ldcs). No barriers after the g stage; per-warp
// shfl reduction and lane-0 epilogue only.
__global__ void __launch_bounds__(256) izh_fused_kernel(
    const float* __restrict__ x_in,
    const float* __restrict__ v,
    const float* __restrict__ u,
    const float* __restrict__ g,
    const float* __restrict__ w,
    const float* __restrict__ a_p,
    const float* __restrict__ b_p,
    const float* __restrict__ c_p,
    const float* __restrict__ d_p,
    float* __restrict__ out)
{
    __shared__ float gs[NN];  // 32 KB -> 7 CTAs/SM

    const int lane = threadIdx.x & 31;
    const int wid  = threadIdx.x >> 5;
    const int row  = blockIdx.x * 8 + wid;

    // Lane 0 of each warp prefetches its row's epilogue scalars early so the
    // DRAM latency overlaps the g staging + w streaming.
    float pre_x = 0.f, pre_v = 0.f, pre_u = 0.f, pre_g = 0.f;
    float pre_a = 0.f, pre_b = 0.f, pre_c = 0.f, pre_d = 0.f;
    if (lane == 0) {
        pre_x = __ldg(&x_in[row]);
        pre_v = __ldg(&v[row]);
        pre_u = __ldg(&u[row]);
        pre_g = __ldg(&g[row]);
        pre_a = __ldg(&a_p[row]);
        pre_b = __ldg(&b_p[row]);
        pre_c = __ldg(&c_p[row]);
        pre_d = __ldg(&d_p[row]);
    }

    // Cooperative stage: g -> smem (2048 float4 over 256 threads).
    {
        const float4* __restrict__ g4 = reinterpret_cast<const float4*>(g);
        float4* gs4 = reinterpret_cast<float4*>(gs);
        #pragma unroll
        for (int i = 0; i < 8; ++i) {
            const int idx = threadIdx.x + i * 256;
            gs4[idx] = __ldg(&g4[idx]);
        }
    }
    __syncthreads();

    const float4* __restrict__ wrow =
        reinterpret_cast<const float4*>(w + (size_t)row * NN);
    const float4* gs4 = reinterpret_cast<const float4*>(gs);

    // 2048 float4 per row / 32 lanes = 64 per lane.
    float sum = 0.0f;
    #pragma unroll 8
    for (int i = 0; i < 64; ++i) {
        const int idx = i * 32 + lane;
        const float4 a = __ldcs(&wrow[idx]);  // streaming: evict-first
        const float4 b = gs4[idx];            // shared pipe, conflict-free
        sum += a.x * b.x;
        sum += a.y * b.y;
        sum += a.z * b.z;
        sum += a.w * b.w;
    }

    // warp-local reduction only — no CTA barrier
    #pragma unroll
    for (int off = 16; off > 0; off >>= 1)
        sum += __shfl_xor_sync(0xffffffffu, sum, off);

    if (lane == 0) {
        const float I  = sum + pre_x;
        const float vv = pre_v;
        const float uu = pre_u;
        const float gg = pre_g;

        // Izhikevich quadratic dynamics
        const float v1 = vv + (0.04f * vv * vv + 5.0f * vv + 140.0f - uu + I);

        // differentiable spike surrogate: sigmoid(4 * (v1 - 30))
        const float s = 1.0f / (1.0f + expf(-4.0f * (v1 - 30.0f)));

        // hard spike mask for state resets
        const float spk = (v1 >= 30.0f) ? 1.0f : 0.0f;
        const float ns  = 1.0f - spk;

        const float du = fabsf(pre_a) * (fabsf(pre_b) * v1 - uu);
        const float dg = -gg / 6.5f;

        out[row]           = ns * v1 + spk * pre_c;           // v_out
        out[NN + row]      = s;                                // spiked_s
        out[2 * NN + row]  = ns * (uu + du) + spk * pre_d;     // u_out
        out[3 * NN + row]  = ns * (gg + dg) + spk;             // g_out
    }
}

extern "C" void kernel_launch(void* const* d_in, const int* in_sizes, int n_in,
                              void* d_out, int out_size)
{
    const float* x_in = (const float*)d_in[0];
    const float* v    = (const float*)d_in[1];
    const float* u    = (const float*)d_in[2];
    const float* g    = (const float*)d_in[3];
    const float* w    = (const float*)d_in[4];
    const float* a_p  = (const float*)d_in[5];
    const float* b_p  = (const float*)d_in[6];
    const float* c_p  = (const float*)d_in[7];
    const float* d_p  = (const float*)d_in[8];
    float* out = (float*)d_out;

    izh_fused_kernel<<<NN / 8, 256>>>(x_in, v, u, g, w, a_p, b_p, c_p, d_p, out);
}

// round 5
// speedup vs baseline: 1.2358x; 1.2358x over previous
#include <cuda_runtime.h>
#include <math.h>

#define NN 8192
#define GRID 1036   // 148 SMs * 7 CTAs/SM -> exactly one wave at 32KB smem

// Persistent CTA-per-row: grid of 1036 CTAs, each grid-strides over ~8 rows.
// g (32 KB) staged to smem ONCE per CTA (33 MB total vs 256 MB of L1tex reads),
// mainloop reads g via the shared pipe. w streamed evict-first with the proven
// round-2 engine: 256 threads x 8 front-batched LDG.128 per row.
__global__ void __launch_bounds__(256) izh_fused_kernel(
    const float* __restrict__ x_in,
    const float* __restrict__ v,
    const float* __restrict__ u,
    const float* __restrict__ g,
    const float* __restrict__ w,
    const float* __restrict__ a_p,
    const float* __restrict__ b_p,
    const float* __restrict__ c_p,
    const float* __restrict__ d_p,
    float* __restrict__ out)
{
    __shared__ float gs[NN];      // 32 KB
    __shared__ float ssum[8];

    const int tid  = threadIdx.x;
    const int lane = tid & 31;
    const int wid  = tid >> 5;

    // Stage g -> smem once per CTA (2048 float4 over 256 threads).
    {
        const float4* __restrict__ g4 = reinterpret_cast<const float4*>(g);
        float4* gs4 = reinterpret_cast<float4*>(gs);
        #pragma unroll
        for (int i = 0; i < 8; ++i) {
            const int idx = tid + i * 256;
            gs4[idx] = __ldg(&g4[idx]);
        }
    }
    __syncthreads();

    const float4* gs4 = reinterpret_cast<const float4*>(gs);

    for (int row = blockIdx.x; row < NN; row += GRID) {
        // Thread 0 prefetches this row's epilogue scalars; latency overlaps
        // the row's own w streaming.
        float pre_x = 0.f, pre_v = 0.f, pre_u = 0.f, pre_g = 0.f;
        float pre_a = 0.f, pre_b = 0.f, pre_c = 0.f, pre_d = 0.f;
        if (tid == 0) {
            pre_x = __ldg(&x_in[row]);
            pre_v = __ldg(&v[row]);
            pre_u = __ldg(&u[row]);
            pre_g = __ldg(&g[row]);
            pre_a = __ldg(&a_p[row]);
            pre_b = __ldg(&b_p[row]);
            pre_c = __ldg(&c_p[row]);
            pre_d = __ldg(&d_p[row]);
        }

        const float4* __restrict__ wrow =
            reinterpret_cast<const float4*>(w + (size_t)row * NN);

        float sum = 0.0f;
        #pragma unroll
        for (int i = 0; i < 8; ++i) {
            const int idx = tid + i * 256;
            const float4 a = __ldcs(&wrow[idx]);  // streaming: evict-first
            const float4 b = gs4[idx];            // shared pipe
            sum += a.x * b.x;
            sum += a.y * b.y;
            sum += a.z * b.z;
            sum += a.w * b.w;
        }

        // intra-warp reduction
        #pragma unroll
        for (int off = 16; off > 0; off >>= 1)
            sum += __shfl_xor_sync(0xffffffffu, sum, off);

        if (lane == 0) ssum[wid] = sum;
        __syncthreads();

        if (tid == 0) {
            float dot = 0.0f;
            #pragma unroll
            for (int i = 0; i < 8; ++i) dot += ssum[i];

            const float I  = dot + pre_x;
            const float vv = pre_v;
            const float uu = pre_u;
            const float gg = pre_g;

            // Izhikevich quadratic dynamics
            const float v1 = vv + (0.04f * vv * vv + 5.0f * vv + 140.0f - uu + I);

            // differentiable spike surrogate: sigmoid(4 * (v1 - 30))
            const float s = 1.0f / (1.0f + expf(-4.0f * (v1 - 30.0f)));

            // hard spike mask for state resets
            const float spk = (v1 >= 30.0f) ? 1.0f : 0.0f;
            const float ns  = 1.0f - spk;

            const float du = fabsf(pre_a) * (fabsf(pre_b) * v1 - uu);
            const float dg = -gg / 6.5f;

            out[row]           = ns * v1 + spk * pre_c;           // v_out
            out[NN + row]      = s;                                // spiked_s
            out[2 * NN + row]  = ns * (uu + du) + spk * pre_d;     // u_out
            out[3 * NN + row]  = ns * (gg + dg) + spk;             // g_out
        }
        __syncthreads();  // protect ssum reuse next iteration
    }
}

extern "C" void kernel_launch(void* const* d_in, const int* in_sizes, int n_in,
                              void* d_out, int out_size)
{
    const float* x_in = (const float*)d_in[0];
    const float* v    = (const float*)d_in[1];
    const float* u    = (const float*)d_in[2];
    const float* g    = (const float*)d_in[3];
    const float* w    = (const float*)d_in[4];
    const float* a_p  = (const float*)d_in[5];
    const float* b_p  = (const float*)d_in[6];
    const float* c_p  = (const float*)d_in[7];
    const float* d_p  = (const float*)d_in[8];
    float* out = (float*)d_out;

    izh_fused_kernel<<<GRID, 256>>>(x_in, v, u, g, w, a_p, b_p, c_p, d_p, out);
}

// round 6
// speedup vs baseline: 1.4113x; 1.1420x over previous
#include <cuda_runtime.h>
#include <math.h>

#define NN 8192

// Round-2 engine (CTA-per-row, 8192 independent CTAs, 256 threads, 8 front-
// batched 128-bit w-loads per thread) + L1::no_allocate on the w stream so w
// never thrashes g out of L1. g stays L1-resident per SM -> g reads are L1
// hits, L2 traffic drops ~2x. No barriers in the streaming path.
__device__ __forceinline__ float4 ldg_stream_noL1(const float4* p) {
    float4 r;
    asm("ld.global.nc.L1::no_allocate.v4.f32 {%0,%1,%2,%3}, [%4];"
        : "=f"(r.x), "=f"(r.y), "=f"(r.z), "=f"(r.w)
        : "l"(p));
    return r;
}

__global__ void __launch_bounds__(256, 8) izh_fused_kernel(
    const float* __restrict__ x_in,
    const float* __restrict__ v,
    const float* __restrict__ u,
    const float* __restrict__ g,
    const float* __restrict__ w,
    const float* __restrict__ a_p,
    const float* __restrict__ b_p,
    const float* __restrict__ c_p,
    const float* __restrict__ d_p,
    float* __restrict__ out)
{
    const int row = blockIdx.x;
    const float4* __restrict__ wrow = reinterpret_cast<const float4*>(w + (size_t)row * NN);
    const float4* __restrict__ g4   = reinterpret_cast<const float4*>(g);

    // Prefetch epilogue scalars early (thread 0 only) so their DRAM latency
    // overlaps the w-row streaming instead of serializing after the reduction.
    float pre_x = 0.f, pre_v = 0.f, pre_u = 0.f, pre_g = 0.f;
    float pre_a = 0.f, pre_b = 0.f, pre_c = 0.f, pre_d = 0.f;
    if (threadIdx.x == 0) {
        pre_x = __ldg(&x_in[row]);
        pre_v = __ldg(&v[row]);
        pre_u = __ldg(&u[row]);
        pre_g = __ldg(&g[row]);
        pre_a = __ldg(&a_p[row]);
        pre_b = __ldg(&b_p[row]);
        pre_c = __ldg(&c_p[row]);
        pre_d = __ldg(&d_p[row]);
    }

    float sum = 0.0f;
    #pragma unroll
    for (int i = 0; i < 8; ++i) {
        const int idx = threadIdx.x + i * 256;
        const float4 a = ldg_stream_noL1(&wrow[idx]);  // w: bypass L1 allocate
        const float4 b = __ldg(&g4[idx]);              // g: L1-resident hits
        sum += a.x * b.x;
        sum += a.y * b.y;
        sum += a.z * b.z;
        sum += a.w * b.w;
    }

    // intra-warp reduction
    #pragma unroll
    for (int off = 16; off > 0; off >>= 1)
        sum += __shfl_xor_sync(0xffffffffu, sum, off);

    __shared__ float ssum[8];
    const int wid = threadIdx.x >> 5;
    if ((threadIdx.x & 31) == 0) ssum[wid] = sum;
    __syncthreads();

    if (threadIdx.x == 0) {
        float dot = 0.0f;
        #pragma unroll
        for (int i = 0; i < 8; ++i) dot += ssum[i];

        const float I  = dot + pre_x;
        const float vv = pre_v;
        const float uu = pre_u;
        const float gg = pre_g;

        // Izhikevich quadratic dynamics
        const float v1 = vv + (0.04f * vv * vv + 5.0f * vv + 140.0f - uu + I);

        // differentiable spike surrogate: sigmoid(4 * (v1 - 30))
        const float s = 1.0f / (1.0f + expf(-4.0f * (v1 - 30.0f)));

        // hard spike mask for state resets
        const float spk = (v1 >= 30.0f) ? 1.0f : 0.0f;
        const float ns  = 1.0f - spk;

        const float du = fabsf(pre_a) * (fabsf(pre_b) * v1 - uu);
        const float dg = -gg / 6.5f;

        out[row]           = ns * v1 + spk * pre_c;           // v_out
        out[NN + row]      = s;                                // spiked_s
        out[2 * NN + row]  = ns * (uu + du) + spk * pre_d;     // u_out
        out[3 * NN + row]  = ns * (gg + dg) + spk;             // g_out
    }
}

extern "C" void kernel_launch(void* const* d_in, const int* in_sizes, int n_in,
                              void* d_out, int out_size)
{
    const float* x_in = (const float*)d_in[0];
    const float* v    = (const float*)d_in[1];
    const float* u    = (const float*)d_in[2];
    const float* g    = (const float*)d_in[3];
    const float* w    = (const float*)d_in[4];
    const float* a_p  = (const float*)d_in[5];
    const float* b_p  = (const float*)d_in[6];
    const float* c_p  = (const float*)d_in[7];
    const float* d_p  = (const float*)d_in[8];
    float* out = (float*)d_out;

    izh_fused_kernel<<<NN, 256>>>(x_in, v, u, g, w, a_p, b_p, c_p, d_p, out);
}